// round 16
// baseline (speedup 1.0000x reference)
#include <cuda_runtime.h>
#include <cuda_fp16.h>
#include <math.h>
#include <stdint.h>

#define MTOT 16384

// ---------------- scratch ----------------
__device__ __align__(1024) __half g_xall[(size_t)MTOT * 512];
__device__ __align__(1024) __half g_q   [(size_t)MTOT * 256];
__device__ __align__(1024) __half g_kv  [(size_t)MTOT * 512];
__device__ __align__(1024) __half g_h1  [(size_t)MTOT * 256];
__device__ __align__(1024) __half g_V   [(size_t)65536 * 256];
__device__ float  g_offs[(size_t)MTOT * 18];
__device__ __align__(1024) __half g_att [(size_t)MTOT * 256];
__device__ float  g_xres[(size_t)MTOT * 256];
__device__ __align__(1024) __half g_xn2 [(size_t)MTOT * 256];
__device__ __align__(1024) __half g_hid [(size_t)MTOT * 1024];
__device__ __align__(1024) __half g_wrw [16 * 256 * 512];
__device__ __align__(1024) __half g_wh  [65536 + 131072 + 65536 + 262144 + 262144];
__device__ float  g_zero[256];
__device__ float2 g_part[256];
__device__ float  g_st1 [16];
__device__ float  g_st2 [8];
__device__ unsigned g_cnt1 = 0;
__device__ unsigned g_cnt2 = 0;
__device__ unsigned g_cnt3 = 0;
__device__ volatile int g_flag = 0;

// ---------------- fused front: weight prep (wino + 5x f2h) + gn1 stats ----------------
__global__ void front_k(const float* __restrict__ off1_w, __half* __restrict__ wrw,
                        const float* __restrict__ q_w,    __half* __restrict__ qwh,
                        const float* __restrict__ kv_w,   __half* __restrict__ kvwh,
                        const float* __restrict__ proj_w, __half* __restrict__ pwh,
                        const float* __restrict__ fc1_w,  __half* __restrict__ f1wh,
                        const float* __restrict__ fc2_w,  __half* __restrict__ f2wh,
                        const float* __restrict__ x_q,    const float* __restrict__ x_kv,
                        float2* __restrict__ part, float* __restrict__ stats) {
    if (blockIdx.x < 3584) {
        int id = blockIdx.x * 256 + threadIdx.x;
        if (id < 131072) {
            int o = id >> 9, c = id & 511;
            const float* g = off1_w + (size_t)(o * 512 + c) * 9;
            float r[4][3];
#pragma unroll
            for (int j = 0; j < 3; j++) {
                float g0 = g[j], g1 = g[3 + j], g2 = g[6 + j];
                r[0][j] = g0;
                r[1][j] = 0.5f * (g0 + g1 + g2);
                r[2][j] = 0.5f * (g0 - g1 + g2);
                r[3][j] = g2;
            }
#pragma unroll
            for (int i = 0; i < 4; i++) {
                float w0 = r[i][0], w1 = 0.5f * (r[i][0] + r[i][1] + r[i][2]);
                float w2 = 0.5f * (r[i][0] - r[i][1] + r[i][2]), w3 = r[i][2];
                wrw[(((size_t)(i * 4 + 0) * 256 + o) << 9) + c] = __float2half(w0);
                wrw[(((size_t)(i * 4 + 1) * 256 + o) << 9) + c] = __float2half(w1);
                wrw[(((size_t)(i * 4 + 2) * 256 + o) << 9) + c] = __float2half(w2);
                wrw[(((size_t)(i * 4 + 3) * 256 + o) << 9) + c] = __float2half(w3);
            }
            return;
        }
        id -= 131072;
        if (id < 65536)  { qwh [id] = __float2half(q_w [id]); return; }  id -= 65536;
        if (id < 131072) { kvwh[id] = __float2half(kv_w[id]); return; }  id -= 131072;
        if (id < 65536)  { pwh [id] = __float2half(proj_w[id]); return; } id -= 65536;
        if (id < 262144) { f1wh[id] = __float2half(fc1_w[id]); return; }  id -= 262144;
        f2wh[id] = __float2half(fc2_w[id]);
        return;
    }
    int bi = blockIdx.x - 3584;
    int slab = bi >> 5, chunk = bi & 31;
    int tensor = slab >> 2, batch = slab & 3;
    const float* src = (tensor ? x_kv : x_q) + ((size_t)batch << 20) + ((size_t)chunk << 15);
    const float4* p4 = reinterpret_cast<const float4*>(src);
    float s = 0.f, s2 = 0.f;
    for (int i = threadIdx.x; i < 8192; i += 256) {
        float4 v = p4[i];
        s  += v.x + v.y + v.z + v.w;
        s2 += v.x * v.x + v.y * v.y + v.z * v.z + v.w * v.w;
    }
    __shared__ float sh1[256], sh2[256];
    sh1[threadIdx.x] = s; sh2[threadIdx.x] = s2;
    __syncthreads();
    for (int st = 128; st > 0; st >>= 1) {
        if (threadIdx.x < st) { sh1[threadIdx.x] += sh1[threadIdx.x + st];
                                sh2[threadIdx.x] += sh2[threadIdx.x + st]; }
        __syncthreads();
    }
    __shared__ bool last;
    if (threadIdx.x == 0) {
        part[slab * 32 + chunk] = make_float2(sh1[0], sh2[0]);
        __threadfence();
        last = (atomicInc(&g_cnt1, 0xFFFFFFFFu) == 255);
    }
    __syncthreads();
    if (!last) return;
    int sl2 = threadIdx.x >> 5, lane = threadIdx.x & 31;
    float a = part[sl2 * 32 + lane].x, b = part[sl2 * 32 + lane].y;
#pragma unroll
    for (int off = 16; off > 0; off >>= 1) {
        a += __shfl_xor_sync(0xffffffffu, a, off);
        b += __shfl_xor_sync(0xffffffffu, b, off);
    }
    if (lane == 0) {
        float inv = 1.f / 1048576.f;
        float mu = a * inv;
        float var = b * inv - mu * mu;
        stats[sl2 * 2] = mu;
        stats[sl2 * 2 + 1] = rsqrtf(var + 1e-5f);
    }
    __syncthreads();
    if (threadIdx.x == 0) g_cnt1 = 0;
}

// ---------------- fused xres stats + norm2 ----------------
__global__ void __launch_bounds__(256) gnxn_k(
    const float* __restrict__ xres, float2* __restrict__ part, float* __restrict__ stats,
    const float* __restrict__ w, const float* __restrict__ bb, __half* __restrict__ xn) {
    int bi = blockIdx.x;
    int slab = bi >> 5, chunk = bi & 31;
    const size_t base4 = ((size_t)slab << 18) + ((size_t)chunk << 13);
    const float4* p4 = reinterpret_cast<const float4*>(xres) + base4;
    float s = 0.f, s2 = 0.f;
    float4 cache[32];
#pragma unroll
    for (int i = 0; i < 32; i++) {
        float4 v = p4[threadIdx.x + (i << 8)];
        cache[i] = v;
        s  += v.x + v.y + v.z + v.w;
        s2 += v.x * v.x + v.y * v.y + v.z * v.z + v.w * v.w;
    }
    __shared__ float sh1[256], sh2[256];
    sh1[threadIdx.x] = s; sh2[threadIdx.x] = s2;
    __syncthreads();
    for (int st = 128; st > 0; st >>= 1) {
        if (threadIdx.x < st) { sh1[threadIdx.x] += sh1[threadIdx.x + st];
                                sh2[threadIdx.x] += sh2[threadIdx.x + st]; }
        __syncthreads();
    }
    __shared__ bool last;
    if (threadIdx.x == 0) {
        part[slab * 32 + chunk] = make_float2(sh1[0], sh2[0]);
        __threadfence();
        last = (atomicInc(&g_cnt2, 0xFFFFFFFFu) == 127);
    }
    __syncthreads();
    if (last) {
        int sl2 = threadIdx.x >> 5, lane = threadIdx.x & 31;
        if (sl2 < 4) {
            float a = part[sl2 * 32 + lane].x, b = part[sl2 * 32 + lane].y;
#pragma unroll
            for (int off = 16; off > 0; off >>= 1) {
                a += __shfl_xor_sync(0xffffffffu, a, off);
                b += __shfl_xor_sync(0xffffffffu, b, off);
            }
            if (lane == 0) {
                float inv = 1.f / 1048576.f;
                float mu = a * inv;
                float var = b * inv - mu * mu;
                stats[sl2 * 2] = mu;
                stats[sl2 * 2 + 1] = rsqrtf(var + 1e-5f);
            }
        }
        __syncthreads();
        if (threadIdx.x == 0) { __threadfence(); g_flag = 1; }
    }
    if (threadIdx.x == 0) { while (g_flag == 0) { } }
    __syncthreads();
    float mu = stats[slab * 2], rstd = stats[slab * 2 + 1];
    uint2* dst = reinterpret_cast<uint2*>(xn) + base4;
#pragma unroll
    for (int i = 0; i < 32; i++) {
        const int e4 = (int)((base4 + threadIdx.x + (i << 8)) & 63);
        const int c = e4 << 2;
        float4 v = cache[i];
        float n0 = (v.x - mu) * rstd * w[c]     + bb[c];
        float n1 = (v.y - mu) * rstd * w[c + 1] + bb[c + 1];
        float n2 = (v.z - mu) * rstd * w[c + 2] + bb[c + 2];
        float n3 = (v.w - mu) * rstd * w[c + 3] + bb[c + 3];
        __half2 h0 = __floats2half2_rn(n0, n1);
        __half2 h1 = __floats2half2_rn(n2, n3);
        uint2 pk;
        pk.x = *reinterpret_cast<uint32_t*>(&h0);
        pk.y = *reinterpret_cast<uint32_t*>(&h1);
        dst[threadIdx.x + (i << 8)] = pk;
    }
    __syncthreads();
    if (threadIdx.x == 0) {
        if (atomicInc(&g_cnt3, 0xFFFFFFFFu) == 127) {
            g_flag = 0; g_cnt2 = 0; g_cnt3 = 0;
            __threadfence();
        }
    }
}

// ---------------- normalize + NCHW->NHWC pack ----------------
__global__ void norm_pack_k(const float* __restrict__ xq, const float* __restrict__ xkv,
                            const float* __restrict__ stats, const float* __restrict__ w,
                            const float* __restrict__ bb, __half* __restrict__ xall) {
    __shared__ float tile[64][33];
    int bz = blockIdx.z;
    int tensor = bz >> 2, batch = bz & 3;
    const float* src = (tensor == 0 ? xq : xkv) + ((size_t)batch << 20);
    float mu = stats[bz * 2], rstd = stats[bz * 2 + 1];
    int s0 = blockIdx.x * 32, c0 = blockIdx.y * 64;
    int tx = threadIdx.x, ty = threadIdx.y;
#pragma unroll
    for (int k = 0; k < 8; k++) {
        int c = c0 + ty + k * 8;
        tile[ty + k * 8][tx] = src[(size_t)c * 4096 + s0 + tx];
    }
    __syncthreads();
    int c = c0 + 2 * tx;
    float w0 = w[c], w1 = w[c + 1], bb0 = bb[c], bb1 = bb[c + 1];
#pragma unroll
    for (int k = 0; k < 4; k++) {
        int sl = ty + k * 8;
        float v0 = (tile[2 * tx][sl] - mu) * rstd * w0 + bb0;
        float v1 = (tile[2 * tx + 1][sl] - mu) * rstd * w1 + bb1;
        __half2 hv = __floats2half2_rn(v0, v1);
        *reinterpret_cast<uint32_t*>(
            xall + (((size_t)batch * 4096 + s0 + sl) << 9) + tensor * 256 + c) =
            *reinterpret_cast<uint32_t*>(&hv);
    }
}

// ---------------- winograd output transform (bias + relu) ----------------
__global__ void wino_out_k(const __half* __restrict__ V, const float* __restrict__ bias,
                           __half* __restrict__ h1) {
    int id = blockIdx.x * 256 + threadIdx.x;
    int o2 = id & 127, t = id >> 7;
    int o = o2 << 1;
    int b = t >> 10, sp = t & 1023, ty = sp >> 5, tx = sp & 31;
    float m0[4][4], m1[4][4];
#pragma unroll
    for (int i = 0; i < 4; i++)
#pragma unroll
        for (int j = 0; j < 4; j++) {
            uint32_t v = *reinterpret_cast<const uint32_t*>(
                V + (((size_t)(i * 4 + j) * 4096 + t) << 8) + o);
            float2 f = __half22float2(*reinterpret_cast<__half2*>(&v));
            m0[i][j] = f.x; m1[i][j] = f.y;
        }
    float b0 = bias[o], b1 = bias[o + 1];
    float p00[4], p01[4], p10[4], p11[4];
#pragma unroll
    for (int j = 0; j < 4; j++) {
        p00[j] = m0[0][j] + m0[1][j] + m0[2][j];
        p01[j] = m0[1][j] - m0[2][j] - m0[3][j];
        p10[j] = m1[0][j] + m1[1][j] + m1[2][j];
        p11[j] = m1[1][j] - m1[2][j] - m1[3][j];
    }
    float y0[2][2], y1[2][2];
    y0[0][0] = p00[0] + p00[1] + p00[2];  y0[0][1] = p00[1] - p00[2] - p00[3];
    y0[1][0] = p01[0] + p01[1] + p01[2];  y0[1][1] = p01[1] - p01[2] - p01[3];
    y1[0][0] = p10[0] + p10[1] + p10[2];  y1[0][1] = p10[1] - p10[2] - p10[3];
    y1[1][0] = p11[0] + p11[1] + p11[2];  y1[1][1] = p11[1] - p11[2] - p11[3];
#pragma unroll
    for (int r = 0; r < 2; r++)
#pragma unroll
        for (int cc = 0; cc < 2; cc++) {
            float v0 = fmaxf(y0[r][cc] + b0, 0.f);
            float v1 = fmaxf(y1[r][cc] + b1, 0.f);
            __half2 hv = __floats2half2_rn(v0, v1);
            int py = (ty << 1) + r, px = (tx << 1) + cc;
            *reinterpret_cast<uint32_t*>(
                h1 + (((size_t)(b << 12) + (py << 6) + px) << 8) + o) =
                *reinterpret_cast<uint32_t*>(&hv);
        }
}

// ---------------- PTX helpers ----------------
__device__ __forceinline__ void mma16(float4& d, const uint32_t* a, const uint32_t* b) {
    asm volatile("mma.sync.aligned.m16n8k16.row.col.f32.f16.f16.f32 "
        "{%0,%1,%2,%3}, {%4,%5,%6,%7}, {%8,%9}, {%0,%1,%2,%3};\n"
        : "+f"(d.x), "+f"(d.y), "+f"(d.z), "+f"(d.w)
        : "r"(a[0]), "r"(a[1]), "r"(a[2]), "r"(a[3]), "r"(b[0]), "r"(b[1]));
}
__device__ __forceinline__ void ldsm4(uint32_t* r, uint32_t a) {
    asm volatile("ldmatrix.sync.aligned.m8n8.x4.shared.b16 {%0,%1,%2,%3}, [%4];"
        : "=r"(r[0]), "=r"(r[1]), "=r"(r[2]), "=r"(r[3]) : "r"(a));
}
__device__ __forceinline__ void cp16(uint32_t d, const void* s, int sz) {
    asm volatile("cp.async.cg.shared.global [%0], [%1], 16, %2;"
        :: "r"(d), "l"(s), "r"(sz));
}
__device__ __forceinline__ void sts16(uint32_t a, const uint32_t* v) {
    asm volatile("st.shared.v4.b32 [%0], {%1,%2,%3,%4};"
        :: "r"(a), "r"(v[0]), "r"(v[1]), "r"(v[2]), "r"(v[3]));
}
#define CP_COMMIT() asm volatile("cp.async.commit_group;")

// ---------------- multi-job fp16 tensor-core GEMM (wino A-transform fused) ----------------
#define STG_BYTES 32768
#define SMEM_REQ  (3 * STG_BYTES)

struct GJob {
    const __half* A; const __half* W; const float* bias; float* C; const float* R;
    int N, K, lda, mode, wino; float scale;
};

__constant__ int   c_P0[4] = {0, 1, 1, 1};
__constant__ int   c_P1[4] = {2, 2, 2, 3};
__constant__ float c_S0[4] = {1.f, 1.f, -1.f, 1.f};
__constant__ float c_S1[4] = {-1.f, 1.f, 1.f, -1.f};

__device__ __forceinline__ void issue_tile(
    uint32_t sa0, const __half* __restrict__ A, const __half* __restrict__ W,
    int bm, int bn, int K0, int lda, int K, int wino, int lrow, int g)
{
    uint32_t sa = sa0 + lrow * 128;
    const int r7 = lrow & 7;
    if (!wino) {
        const __half* srcA = A + (size_t)(bm + lrow) * lda + K0;
#pragma unroll
        for (int j = 0; j < 4; j++) {
            const int c = g + j;
            cp16(sa + (uint32_t)((c ^ r7) << 4), srcA + c * 8, 16);
        }
    } else {
        // on-the-fly F(2x2,3x3) input transform: U[s][t][c] from xall
        const int srow = bm >> 12;
        const int si = srow >> 2, sj = srow & 3;
        const int t = (bm & 4095) + lrow;
        const int b = t >> 10, sp = t & 1023;
        const int py = ((sp >> 5) << 1) - 1, px = ((sp & 31) << 1) - 1;
        const int r0 = py + c_P0[si], r1 = py + c_P1[si];
        const int cc0 = px + c_P0[sj], cc1 = px + c_P1[sj];
        const float s00 = c_S0[si] * c_S0[sj], s01 = c_S0[si] * c_S1[sj];
        const float s10 = c_S1[si] * c_S0[sj], s11 = c_S1[si] * c_S1[sj];
        const bool vr0 = (unsigned)r0 < 64u, vr1 = (unsigned)r1 < 64u;
        const bool vc0 = (unsigned)cc0 < 64u, vc1 = (unsigned)cc1 < 64u;
        const bool v00 = vr0 && vc0, v01 = vr0 && vc1, v10 = vr1 && vc0, v11 = vr1 && vc1;
        const __half* base = A + (((size_t)(b << 12)) << 9);
        const __half* q00 = base + ((((r0 & 63) << 6) + (cc0 & 63)) << 9);
        const __half* q01 = base + ((((r0 & 63) << 6) + (cc1 & 63)) << 9);
        const __half* q10 = base + ((((r1 & 63) << 6) + (cc0 & 63)) << 9);
        const __half* q11 = base + ((((r1 & 63) << 6) + (cc1 & 63)) << 9);
        const uint4 zz = make_uint4(0, 0, 0, 0);
#pragma unroll
        for (int j = 0; j < 4; j++) {
            const int cc = K0 + (g + j) * 8;
            uint4 u00 = v00 ? *reinterpret_cast<const uint4*>(q00 + cc) : zz;
            uint4 u01 = v01 ? *reinterpret_cast<const uint4*>(q01 + cc) : zz;
            uint4 u10 = v10 ? *reinterpret_cast<const uint4*>(q10 + cc) : zz;
            uint4 u11 = v11 ? *reinterpret_cast<const uint4*>(q11 + cc) : zz;
            const __half2* h00 = reinterpret_cast<const __half2*>(&u00);
            const __half2* h01 = reinterpret_cast<const __half2*>(&u01);
            const __half2* h10 = reinterpret_cast<const __half2*>(&u10);
            const __half2* h11 = reinterpret_cast<const __half2*>(&u11);
            uint32_t outw[4];
#pragma unroll
            for (int l = 0; l < 4; l++) {
                float2 f00 = __half22float2(h00[l]);
                float2 f01 = __half22float2(h01[l]);
                float2 f10 = __half22float2(h10[l]);
                float2 f11 = __half22float2(h11[l]);
                float rx = s00 * f00.x + s01 * f01.x + s10 * f10.x + s11 * f11.x;
                float ry = s00 * f00.y + s01 * f01.y + s10 * f10.y + s11 * f11.y;
                __half2 hv = __floats2half2_rn(rx, ry);
                outw[l] = *reinterpret_cast<uint32_t*>(&hv);
            }
            sts16(sa + (uint32_t)(((g + j) ^ r7) << 4), outw);
        }
    }
    const __half* srcB = W + (size_t)(bn + lrow) * (size_t)K + K0;
#pragma unroll
    for (int j = 0; j < 4; j++) {
        const int c = g + j;
        cp16(sa + 16384 + (uint32_t)((c ^ r7) << 4), srcB + c * 8, 16);
    }
}

__global__ void __launch_bounds__(256, 2) gemm_tc(
    GJob j0, GJob j1, GJob j2, int c0, int c1)
{
    extern __shared__ float smbuf[];
    const uint32_t smem_base = (uint32_t)__cvta_generic_to_shared(smbuf);

    GJob J;
    int local;
    {
        const int id = blockIdx.x;
        if (id < c0)      { J = j0; local = id; }
        else if (id < c1) { J = j1; local = id - c0; }
        else              { J = j2; local = id - c1; }
    }
    const int bnb = J.N >> 7;
    const int bm = (local / bnb) << 7, bn = (local % bnb) << 7;
    if (J.wino) J.W += ((size_t)(bm >> 12)) << 17;

    const int tid  = threadIdx.x;
    const int warp = tid >> 5, lane = tid & 31;
    const int wm   = (warp >> 2) << 6, wn = (warp & 3) << 5;
    const int lg   = lane >> 2, la3 = lane & 3;

    const int lrow = tid >> 1, g = (tid & 1) * 4;

    const int l7 = lane & 7, lq = lane >> 3;
    uint32_t arow[4], brow[2];
#pragma unroll
    for (int mt = 0; mt < 4; mt++)
        arow[mt] = (uint32_t)((wm + mt * 16 + ((lq & 1) << 3) + l7) * 128);
    const int a_kq = lq >> 1;
#pragma unroll
    for (int p = 0; p < 2; p++)
        brow[p] = (uint32_t)(16384 + (wn + p * 16 + ((lq >> 1) << 3) + l7) * 128);
    const int b_kq = lq & 1;

    float4 acc[4][4];
#pragma unroll
    for (int i = 0; i < 4; i++)
#pragma unroll
        for (int j = 0; j < 4; j++) acc[i][j] = make_float4(0.f, 0.f, 0.f, 0.f);

    const int nkb = J.K >> 6;
    issue_tile(smem_base,             J.A, J.W, bm, bn,  0, J.lda, J.K, J.wino, lrow, g);
    CP_COMMIT();
    issue_tile(smem_base + STG_BYTES, J.A, J.W, bm, bn, 64, J.lda, J.K, J.wino, lrow, g);
    CP_COMMIT();

    int stg = 0;
    for (int kb = 0; kb < nkb; kb++) {
        asm volatile("cp.async.wait_group 1;");
        __syncthreads();
        if (kb + 2 < nkb) {
            int s2 = stg + 2; if (s2 >= 3) s2 -= 3;
            issue_tile(smem_base + s2 * STG_BYTES, J.A, J.W, bm, bn,
                       (kb + 2) << 6, J.lda, J.K, J.wino, lrow, g);
        }
        CP_COMMIT();

        const uint32_t Ab = smem_base + stg * STG_BYTES;
#pragma unroll
        for (int ks = 0; ks < 4; ks++) {
            const uint32_t axor = (uint32_t)((((ks << 1) + a_kq) ^ l7) << 4);
            const uint32_t bxor = (uint32_t)((((ks << 1) + b_kq) ^ l7) << 4);
            uint32_t af[4][4], bf[2][4];
#pragma unroll
            for (int mt = 0; mt < 4; mt++) ldsm4(af[mt], Ab + arow[mt] + axor);
#pragma unroll
            for (int p = 0; p < 2; p++)    ldsm4(bf[p],  Ab + brow[p] + bxor);
#pragma unroll
            for (int mt = 0; mt < 4; mt++) {
                mma16(acc[mt][0], af[mt], &bf[0][0]);
                mma16(acc[mt][1], af[mt], &bf[0][2]);
                mma16(acc[mt][2], af[mt], &bf[1][0]);
                mma16(acc[mt][3], af[mt], &bf[1][2]);
            }
        }
        if (++stg == 3) stg = 0;
    }

    // ---------------- epilogue ----------------
    const bool halfout = (J.mode == 1) || (J.mode == 2) || (J.mode == 3) || (J.mode == 6);
#pragma unroll
    for (int mt = 0; mt < 4; mt++) {
        const int m0 = bm + wm + (mt << 4) + lg;
#pragma unroll
        for (int nt = 0; nt < 4; nt++) {
            const int n = bn + wn + (nt << 3) + (la3 << 1);
            const float b0 = J.bias[n], b1 = J.bias[n + 1];
            float v[4] = {acc[mt][nt].x + b0, acc[mt][nt].y + b1,
                          acc[mt][nt].z + b0, acc[mt][nt].w + b1};
#pragma unroll
            for (int h = 0; h < 2; h++) {
                const int m = m0 + h * 8;
                if (halfout) {
                    float x0 = v[h * 2], x1 = v[h * 2 + 1];
                    if (J.mode == 1) { x0 *= J.scale; x1 *= J.scale; }
                    else if (J.mode == 2) { x0 = fmaxf(x0, 0.f); x1 = fmaxf(x1, 0.f); }
                    else if (J.mode == 3) {
                        x0 = 0.5f * x0 * (1.f + erff(x0 * 0.70710678118654752f));
                        x1 = 0.5f * x1 * (1.f + erff(x1 * 0.70710678118654752f));
                    }
                    *reinterpret_cast<__half2*>(
                        reinterpret_cast<__half*>(J.C) + (size_t)m * (size_t)J.N + n) =
                        __floats2half2_rn(x0, x1);
                } else {
#pragma unroll
                    for (int j = 0; j < 2; j++) {
                        float x = v[h * 2 + j];
                        const int nn = n + j;
                        if (J.mode == 4) x += J.R[((size_t)(m >> 12) * 256 + nn) * 4096 + (m & 4095)];
                        else if (J.mode == 5) x += J.R[(size_t)m * 256 + nn];
                        if (J.mode == 5)
                            J.C[((size_t)(m >> 12) * 256 + nn) * 4096 + (m & 4095)] = x;
                        else
                            J.C[(size_t)m * (size_t)J.N + nn] = x;
                    }
                }
            }
        }
    }
}

// ---------------- offset head (fp16 h1) ----------------
__global__ void off2_k(const __half* __restrict__ h1, const float* __restrict__ w,
                       const float* __restrict__ bias, float* __restrict__ offs) {
    int id = blockIdx.x * blockDim.x + threadIdx.x;
    if (id >= MTOT * 18) return;
    int m = id / 18, n = id - m * 18;
    const uint4* a = reinterpret_cast<const uint4*>(h1 + (size_t)m * 256);
    const float4* ww = reinterpret_cast<const float4*>(w + (size_t)n * 256);
    float s = bias[n];
#pragma unroll 8
    for (int k = 0; k < 32; k++) {
        uint4 av = a[k];
        const __half2* hh = reinterpret_cast<const __half2*>(&av);
        float2 f0 = __half22float2(hh[0]), f1 = __half22float2(hh[1]);
        float2 f2 = __half22float2(hh[2]), f3 = __half22float2(hh[3]);
        float4 w0 = ww[2 * k], w1 = ww[2 * k + 1];
        s += f0.x * w0.x + f0.y * w0.y + f1.x * w0.z + f1.y * w0.w;
        s += f2.x * w1.x + f2.y * w1.y + f3.x * w1.z + f3.y * w1.w;
    }
    offs[id] = s;
}

// ---------------- fused bilinear-sample + 9-way attention (fp16) ----------------
#define LOAD8H(dst, ptr)                                                    \
    {                                                                       \
        uint4 _u = *reinterpret_cast<const uint4*>(ptr);                    \
        __half2* _hh = reinterpret_cast<__half2*>(&_u);                     \
        float2 _f0 = __half22float2(_hh[0]), _f1 = __half22float2(_hh[1]);  \
        float2 _f2 = __half22float2(_hh[2]), _f3 = __half22float2(_hh[3]);  \
        dst[0] = _f0.x; dst[1] = _f0.y; dst[2] = _f1.x; dst[3] = _f1.y;     \
        dst[4] = _f2.x; dst[5] = _f2.y; dst[6] = _f3.x; dst[7] = _f3.y;     \
    }

__global__ void __launch_bounds__(256) attn_k(
    const __half* __restrict__ qb, const __half* __restrict__ kv,
    const float* __restrict__ offs, __half* __restrict__ outp) {
    __shared__ float sh[8][9][8];
    const int warp = threadIdx.x >> 5, lane = threadIdx.x & 31;
    const int p = blockIdx.x * 8 + warp;
    const int b = p >> 12, s = p & 4095, y = s >> 6, x = s & 63;
    const __half* kvb = kv + (((size_t)b << 12) << 9);

    float qr[8];
    LOAD8H(qr, qb + (size_t)p * 256 + lane * 8);

    for (int o = 0; o < 9; o++) {
        int ys = y + o / 3 - 1, xs = x + o % 3 - 1;
        float prod[8] = {0.f, 0.f, 0.f, 0.f, 0.f, 0.f, 0.f, 0.f};
        if (ys >= 0 && ys < 64 && xs >= 0 && xs < 64) {
            const float* op = offs + (size_t)((b << 12) + (ys << 6) + xs) * 18 + 2 * o;
            float px = op[0], py = op[1];
            float y0f = floorf(py), x0f = floorf(px);
            float wy = py - y0f, wx = px - x0f;
            int y0 = (int)y0f, x0 = (int)x0f;
            float w00 = (1.f - wy) * (1.f - wx), w01 = (1.f - wy) * wx;
            float w10 = wy * (1.f - wx), w11 = wy * wx;
            bool vy0 = (y0 >= 0) && (y0 < 64), vy1 = (y0 + 1 >= 0) && (y0 + 1 < 64);
            bool vx0 = (x0 >= 0) && (x0 < 64), vx1 = (x0 + 1 >= 0) && (x0 + 1 < 64);
            w00 = (vy0 && vx0) ? w00 : 0.f; w01 = (vy0 && vx1) ? w01 : 0.f;
            w10 = (vy1 && vx0) ? w10 : 0.f; w11 = (vy1 && vx1) ? w11 : 0.f;
            int y0c = min(max(y0, 0), 63), y1c = min(max(y0 + 1, 0), 63);
            int x0c = min(max(x0, 0), 63), x1c = min(max(x0 + 1, 0), 63);
            float c00[8], c01[8], c10[8], c11[8];
            LOAD8H(c00, kvb + ((size_t)((y0c << 6) + x0c) << 9) + lane * 8);
            LOAD8H(c01, kvb + ((size_t)((y0c << 6) + x1c) << 9) + lane * 8);
            LOAD8H(c10, kvb + ((size_t)((y1c << 6) + x0c) << 9) + lane * 8);
            LOAD8H(c11, kvb + ((size_t)((y1c << 6) + x1c) << 9) + lane * 8);
#pragma unroll
            for (int h = 0; h < 8; h++) {
                float kvv = w00 * c00[h] + w01 * c01[h] + w10 * c10[h] + w11 * c11[h];
                prod[h] = qr[h] * kvv;
            }
        }
#pragma unroll
        for (int off = 16; off > 0; off >>= 1)
#pragma unroll
            for (int h = 0; h < 8; h++)
                prod[h] += __shfl_xor_sync(0xffffffffu, prod[h], off);
        if (lane == 0) {
#pragma unroll
            for (int h = 0; h < 8; h++) sh[warp][o][h] = prod[h];
        }
    }
    __syncwarp();
    if (lane < 8) {
        float e[9]; float mx = -1e30f;
#pragma unroll
        for (int o = 0; o < 9; o++) { e[o] = sh[warp][o][lane]; mx = fmaxf(mx, e[o]); }
        float sm = 0.f;
#pragma unroll
        for (int o = 0; o < 9; o++) { e[o] = expf(e[o] - mx); sm += e[o]; }
        float inv = 1.f / sm;
#pragma unroll
        for (int o = 0; o < 9; o++) sh[warp][o][lane] = e[o] * inv;
    }
    __syncwarp();
    float acc[8] = {0.f, 0.f, 0.f, 0.f, 0.f, 0.f, 0.f, 0.f};
    for (int o = 0; o < 9; o++) {
        int ys = y + o / 3 - 1, xs = x + o % 3 - 1;
        if (ys < 0 || ys >= 64 || xs < 0 || xs >= 64) continue;
        const float* op = offs + (size_t)((b << 12) + (ys << 6) + xs) * 18 + 2 * o;
        float px = op[0], py = op[1];
        float y0f = floorf(py), x0f = floorf(px);
        float wy = py - y0f, wx = px - x0f;
        int y0 = (int)y0f, x0 = (int)x0f;
        float w00 = (1.f - wy) * (1.f - wx), w01 = (1.f - wy) * wx;
        float w10 = wy * (1.f - wx), w11 = wy * wx;
        bool vy0 = (y0 >= 0) && (y0 < 64), vy1 = (y0 + 1 >= 0) && (y0 + 1 < 64);
        bool vx0 = (x0 >= 0) && (x0 < 64), vx1 = (x0 + 1 >= 0) && (x0 + 1 < 64);
        w00 = (vy0 && vx0) ? w00 : 0.f; w01 = (vy0 && vx1) ? w01 : 0.f;
        w10 = (vy1 && vx0) ? w10 : 0.f; w11 = (vy1 && vx1) ? w11 : 0.f;
        int y0c = min(max(y0, 0), 63), y1c = min(max(y0 + 1, 0), 63);
        int x0c = min(max(x0, 0), 63), x1c = min(max(x0 + 1, 0), 63);
        float c00[8], c01[8], c10[8], c11[8];
        LOAD8H(c00, kvb + ((size_t)((y0c << 6) + x0c) << 9) + 256 + lane * 8);
        LOAD8H(c01, kvb + ((size_t)((y0c << 6) + x1c) << 9) + 256 + lane * 8);
        LOAD8H(c10, kvb + ((size_t)((y1c << 6) + x0c) << 9) + 256 + lane * 8);
        LOAD8H(c11, kvb + ((size_t)((y1c << 6) + x1c) << 9) + 256 + lane * 8);
#pragma unroll
        for (int h = 0; h < 8; h++) {
            float vv = w00 * c00[h] + w01 * c01[h] + w10 * c10[h] + w11 * c11[h];
            acc[h] += sh[warp][o][h] * vv;
        }
    }
    __half2 h0 = __floats2half2_rn(acc[0], acc[1]);
    __half2 h1 = __floats2half2_rn(acc[2], acc[3]);
    __half2 h2 = __floats2half2_rn(acc[4], acc[5]);
    __half2 h3 = __floats2half2_rn(acc[6], acc[7]);
    uint4 pk;
    pk.x = *reinterpret_cast<uint32_t*>(&h0);
    pk.y = *reinterpret_cast<uint32_t*>(&h1);
    pk.z = *reinterpret_cast<uint32_t*>(&h2);
    pk.w = *reinterpret_cast<uint32_t*>(&h3);
    *reinterpret_cast<uint4*>(outp + (size_t)p * 256 + lane * 8) = pk;
}

// ---------------- host ----------------
extern "C" void kernel_launch(void* const* d_in, const int* in_sizes, int n_in,
                              void* d_out, int out_size) {
    const float* x_q    = (const float*)d_in[0];
    const float* x_kv   = (const float*)d_in[1];
    const float* n1w    = (const float*)d_in[2];
    const float* n1b    = (const float*)d_in[3];
    const float* q_w    = (const float*)d_in[4];
    const float* q_b    = (const float*)d_in[5];
    const float* kv_w   = (const float*)d_in[6];
    const float* kv_b   = (const float*)d_in[7];
    const float* off1_w = (const float*)d_in[8];
    const float* off1_b = (const float*)d_in[9];
    const float* off2_w = (const float*)d_in[10];
    const float* off2_b = (const float*)d_in[11];
    const float* proj_w = (const float*)d_in[12];
    const float* proj_b = (const float*)d_in[13];
    const float* n2w    = (const float*)d_in[14];
    const float* n2b    = (const float*)d_in[15];
    const float* fc1_w  = (const float*)d_in[16];
    const float* fc1_b  = (const float*)d_in[17];
    const float* fc2_w  = (const float*)d_in[18];
    const float* fc2_b  = (const float*)d_in[19];
    float* out = (float*)d_out;

    __half *xall, *qb, *kvb, *h1, *att, *xn2, *hid, *wrw, *wh, *V;
    float *offs, *xres, *st1, *st2, *zerob;
    float2* part;
    cudaGetSymbolAddress((void**)&xall, g_xall);
    cudaGetSymbolAddress((void**)&qb,   g_q);
    cudaGetSymbolAddress((void**)&kvb,  g_kv);
    cudaGetSymbolAddress((void**)&h1,   g_h1);
    cudaGetSymbolAddress((void**)&V,    g_V);
    cudaGetSymbolAddress((void**)&offs, g_offs);
    cudaGetSymbolAddress((void**)&att,  g_att);
    cudaGetSymbolAddress((void**)&xres, g_xres);
    cudaGetSymbolAddress((void**)&xn2,  g_xn2);
    cudaGetSymbolAddress((void**)&hid,  g_hid);
    cudaGetSymbolAddress((void**)&wrw,  g_wrw);
    cudaGetSymbolAddress((void**)&wh,   g_wh);
    cudaGetSymbolAddress((void**)&zerob,g_zero);
    cudaGetSymbolAddress((void**)&part, g_part);
    cudaGetSymbolAddress((void**)&st1,  g_st1);
    cudaGetSymbolAddress((void**)&st2,  g_st2);

    __half* qwh  = wh;
    __half* kvwh = qwh  + 65536;
    __half* pwh  = kvwh + 131072;
    __half* f1wh = pwh  + 65536;
    __half* f2wh = f1wh + 262144;

    cudaFuncSetAttribute(gemm_tc, cudaFuncAttributeMaxDynamicSharedMemorySize, SMEM_REQ);

    front_k<<<3840, 256>>>(off1_w, wrw, q_w, qwh, kv_w, kvwh, proj_w, pwh,
                           fc1_w, f1wh, fc2_w, f2wh, x_q, x_kv, part, st1);
    norm_pack_k<<<dim3(128, 4, 8), dim3(32, 8)>>>(x_q, x_kv, st1, n1w, n1b, xall);

    GJob zero = {};
    // fused winograd-conv (A-transform in loader) + kv + q
    {
        GJob jw  = {xall,        wrw,  zerob, (float*)V,   nullptr, 256, 512, 512, 6, 1, 0.f};
        GJob jkv = {xall + 256,  kvwh, kv_b,  (float*)kvb, nullptr, 512, 256, 512, 6, 0, 0.f};
        GJob jq  = {xall,        qwh,  q_b,   (float*)qb,  nullptr, 256, 256, 512, 1, 0,
                    0.17677669529663689f};
        gemm_tc<<<1792, 256, SMEM_REQ>>>(jw, jkv, jq, 1024, 1536);
    }
    wino_out_k<<<2048, 256>>>(V, off1_b, h1);
    off2_k<<<(MTOT * 18) / 256, 256>>>(h1, off2_w, off2_b, offs);
    attn_k<<<2048, 256>>>(qb, kvb, offs, att);
    // xres = x_q + att @ proj_w^T + b
    {
        GJob jp = {att, pwh, proj_b, xres, x_q, 256, 256, 256, 4, 0, 0.f};
        gemm_tc<<<256, 256, SMEM_REQ>>>(jp, zero, zero, 256, 256);
    }
    gnxn_k<<<128, 256>>>(xres, part, st2, n2w, n2b, xn2);
    // hid = gelu(xn2 @ fc1_w^T + b) -> half
    {
        GJob jf1 = {xn2, f1wh, fc1_b, (float*)hid, nullptr, 1024, 256, 256, 3, 0, 0.f};
        gemm_tc<<<1024, 256, SMEM_REQ>>>(jf1, zero, zero, 1024, 1024);
    }
    // out(NCHW) = xres + hid @ fc2_w^T + b
    {
        GJob jf2 = {hid, f2wh, fc2_b, out, xres, 256, 1024, 1024, 5, 0, 0.f};
        gemm_tc<<<256, 256, SMEM_REQ>>>(jf2, zero, zero, 256, 256);
    }
}